// round 16
// baseline (speedup 1.0000x reference)
#include <cuda_runtime.h>
#include <cuda_bf16.h>

#define TT 100
#define BB 2048
#define NROWS (TT*BB)
#define LOG2PI 1.8378770664093453f

typedef unsigned long long u64t;

// ---------------- packed f32x2 helpers (sm_100+) ----------------
__device__ __forceinline__ u64t pack2(float lo, float hi){
    u64t r; asm("mov.b64 %0, {%1,%2};" : "=l"(r) : "f"(lo), "f"(hi)); return r;
}
__device__ __forceinline__ u64t dup2(float v){ return pack2(v, v); }
__device__ __forceinline__ void unpack2(u64t v, float &lo, float &hi){
    asm("mov.b64 {%0,%1}, %2;" : "=f"(lo), "=f"(hi) : "l"(v));
}
__device__ __forceinline__ void fma2(u64t &d, u64t a, u64t b){
    asm("fma.rn.f32x2 %0, %1, %2, %3;" : "=l"(d) : "l"(a), "l"(b), "l"(d));
}

// ---------------- cp.async helpers ----------------
__device__ __forceinline__ void cp_async8(void* s, const void* g){
    unsigned saddr = (unsigned)__cvta_generic_to_shared(s);
    asm volatile("cp.async.ca.shared.global [%0], [%1], 8;" :: "r"(saddr), "l"(g));
}
#define CP_COMMIT() asm volatile("cp.async.commit_group;" ::: "memory")
#define CP_WAIT0()  asm volatile("cp.async.wait_group 0;" ::: "memory")

// two rows sharing weight loads: acc{0,1}[0..14] += d{0,1} * wrow[0..29]
__device__ __forceinline__ void axpy30x2(u64t* acc0, u64t* acc1, u64t d0, u64t d1,
                                         const float* __restrict__ wrow){
    const ulonglong2* w = (const ulonglong2*)wrow;
    #pragma unroll
    for (int q=0;q<7;q++){
        ulonglong2 ww = w[q];
        fma2(acc0[2*q  ], d0, ww.x); fma2(acc1[2*q  ], d1, ww.x);
        fma2(acc0[2*q+1], d0, ww.y); fma2(acc1[2*q+1], d1, ww.y);
    }
    u64t tail = ((const u64t*)wrow)[14];
    fma2(acc0[14], d0, tail); fma2(acc1[14], d1, tail);
}

// two dot-products (rows A,B) vs one 30-wide weight row; 2 accumulators per row (ILP)
__device__ __forceinline__ void dot30x2(const u64t* hpA, const u64t* hpB,
                                        const float* __restrict__ wrow, float bias,
                                        float &ra, float &rb){
    const ulonglong2* w = (const ulonglong2*)wrow;
    u64t aA0 = pack2(bias, 0.0f), aA1 = pack2(0.0f, 0.0f);
    u64t aB0 = pack2(bias, 0.0f), aB1 = pack2(0.0f, 0.0f);
    #pragma unroll
    for (int q=0;q<7;q++){
        ulonglong2 ww = w[q];
        fma2(aA0, hpA[2*q  ], ww.x); fma2(aB0, hpB[2*q  ], ww.x);
        fma2(aA1, hpA[2*q+1], ww.y); fma2(aB1, hpB[2*q+1], ww.y);
    }
    u64t tail = ((const u64t*)wrow)[14];
    fma2(aA0, hpA[14], tail); fma2(aB0, hpB[14], tail);
    float l0,h0,l1,h1;
    unpack2(aA0,l0,h0); unpack2(aA1,l1,h1); ra = (l0+l1)+(h0+h1);
    unpack2(aB0,l0,h0); unpack2(aB1,l1,h1); rb = (l0+l1)+(h0+h1);
}

// ---------------- scratch ----------------
__device__ float  g_ctx[NROWS*3];
__device__ float  g_zs [NROWS*6];
__device__ double g_acc[3];          // zero at load; finalize block resets after read
__device__ unsigned int g_done;

__device__ __forceinline__ float sp_f(float x){
    float e = __expf(-fabsf(x));
    return fmaxf(x, 0.0f) + __logf(1.0f + e);
}
__device__ __forceinline__ float clamp6f(float x){
    return fminf(fmaxf(x, -6.0f), 6.0f);
}

// ---------------- encoder: 150 -> 30 -> 30 -> {ctx:3, qz0:12}, 2 rows/thread ----------------
// cp.async staging in 15 chunks of 10 floats (tile 10.2KB); set-A activations
// spill into the tile after layer 1 (15.36KB), set-B stays in registers.
// Total smem 41.2KB + <=102 regs -> 5 blocks/SM (occ 4->5 blocks).
#define ENC_TPB 128
#define ENC_NT  (NROWS/2)
#define ENC_CH  5                        // float2 per chunk-row per set
#define ENC_TILE_F2 (ENC_TPB*ENC_CH)     // 640 float2 per set
#define ENC_DYN (ENC_TPB*30*4)           // 15360 B (act region >= 2*640*8 staging)

__global__ void __launch_bounds__(ENC_TPB, 5) k_enc(
    const float* __restrict__ xs,
    const float* __restrict__ eW1, const float* __restrict__ eb1,
    const float* __restrict__ eW2, const float* __restrict__ eb2,
    const float* __restrict__ eW3, const float* __restrict__ eb3,
    const float* __restrict__ eps0,
    const float* __restrict__ pz0m, const float* __restrict__ pz0l)
{
    extern __shared__ __align__(16) float2 tile[];   // staging [2][640] f2; later actA [128][30] f
    float2* tTA = tile;
    float2* tTB = tile + ENC_TILE_F2;
    __shared__ __align__(16) float sW1p[150*32];
    __shared__ __align__(16) float sW2p[30*32];
    __shared__ __align__(16) float sW3c[30*4];
    __shared__ float sW3[450], sb1[30], sb2[30], sb3[15];

    for (int idx=threadIdx.x; idx<150*32; idx+=ENC_TPB){
        int i=idx>>5, j=idx&31;
        sW1p[idx] = (j<30)? eW1[i*30+j] : 0.0f;
    }
    for (int idx=threadIdx.x; idx<30*32; idx+=ENC_TPB){
        int i=idx>>5, j=idx&31;
        sW2p[idx] = (j<30)? eW2[i*30+j] : 0.0f;
    }
    for (int idx=threadIdx.x; idx<30*4; idx+=ENC_TPB){
        int i=idx>>2, c=idx&3;
        sW3c[idx] = (c<3)? eW3[i*15+12+c] : 0.0f;
    }
    for (int i=threadIdx.x;i<450;i+=ENC_TPB) sW3[i]=eW3[i];
    if (threadIdx.x<30){ sb1[threadIdx.x]=eb1[threadIdx.x]; sb2[threadIdx.x]=eb2[threadIdx.x]; }
    if (threadIdx.x<15)  sb3[threadIdx.x]=eb3[threadIdx.x];

    int t = threadIdx.x;
    long baseA = (long)blockIdx.x*ENC_TPB;
    long baseB = baseA + ENC_NT;
    long rA = baseA + t, rB = baseB + t;

    // copy decomposition: idx = t + k*128 over 640 f2; row = idx/5, col = idx%5
    int rowInit = t/5;
    int colInit = t - rowInit*5;

    // ---- layer 1 (packed accumulators, 2 rows share weight loads, staged xs) ----
    u64t A0[15], A1[15];
    #pragma unroll
    for (int q=0;q<15;q++){ u64t b = pack2(eb1[2*q], eb1[2*q+1]); A0[q]=b; A1[q]=b; }

    for (int c=0;c<15;c++){
        __syncthreads();
        {
            const float* pA = xs + (baseA + rowInit)*150 + c*10 + colInit*2;
            const float* pB = xs + (baseB + rowInit)*150 + c*10 + colInit*2;
            int col = colInit;
            int sidx = t;
            #pragma unroll
            for (int k=0;k<5;k++){
                cp_async8(&tTA[sidx], pA);
                cp_async8(&tTB[sidx], pB);
                sidx += ENC_TPB;
                pA += 3756; pB += 3756;   // row += 25, col += 3 (25*150 + 3*2)
                col += 3;
                if (col >= 5){ col -= 5; pA += 140; pB += 140; }  // extra row advance
            }
        }
        CP_COMMIT(); CP_WAIT0();
        __syncthreads();

        const float2* sA = tTA + t*ENC_CH;
        const float2* sB = tTB + t*ENC_CH;
        #pragma unroll
        for (int q=0;q<ENC_CH;q++){
            float2 vA = sA[q], vB = sB[q];
            int i = c*10 + 2*q;
            axpy30x2(A0, A1, dup2(vA.x), dup2(vB.x), sW1p + (i  )*32);
            axpy30x2(A0, A1, dup2(vA.y), dup2(vB.y), sW1p + (i+1)*32);
        }
    }

    // ---- softplus: set-A acts -> smem tile (reused); set-B acts -> registers ----
    __syncthreads();                      // staging reads complete before overwrite
    float* actA = (float*)tile + t*30;    // [128][30] floats
    float a1r[30];
    #pragma unroll
    for (int q=0;q<15;q++){
        float x0,x1,y0,y1;
        unpack2(A0[q], x0, x1);
        unpack2(A1[q], y0, y1);
        actA[2*q]   = sp_f(x0);
        actA[2*q+1] = sp_f(x1);
        a1r[2*q]    = sp_f(y0);
        a1r[2*q+1]  = sp_f(y1);
    }
    // A dead; no sync needed — each thread reads only its own actA row.

    // ---- layer 2 (set-A multipliers from smem, set-B from regs) ----
    u64t B0[15], B1[15];
    #pragma unroll
    for (int q=0;q<15;q++){ u64t b = pack2(sb2[2*q], sb2[2*q+1]); B0[q]=b; B1[q]=b; }
    #pragma unroll 6
    for (int i=0;i<30;i++){
        axpy30x2(B0, B1, dup2(actA[i]), dup2(a1r[i]), sW2p + i*32);
    }
    float b0[30], b1[30];
    #pragma unroll
    for (int q=0;q<15;q++){
        unpack2(B0[q], b0[2*q], b0[2*q+1]);
        unpack2(B1[q], b1[2*q], b1[2*q+1]);
    }
    #pragma unroll
    for (int j=0;j<30;j++){ b0[j]=sp_f(b0[j]); b1[j]=sp_f(b1[j]); }

    // ---- layer 3, ctx cols ----
    float c00=sb3[12], c01=sb3[13], c02=sb3[14];
    float c10=sb3[12], c11=sb3[13], c12=sb3[14];
    #pragma unroll
    for (int i=0;i<30;i++){
        float4 w = ((const float4*)sW3c)[i];
        c00=fmaf(b0[i],w.x,c00); c01=fmaf(b0[i],w.y,c01); c02=fmaf(b0[i],w.z,c02);
        c10=fmaf(b1[i],w.x,c10); c11=fmaf(b1[i],w.y,c11); c12=fmaf(b1[i],w.z,c12);
    }
    g_ctx[rA*3+0]=c00; g_ctx[rA*3+1]=c01; g_ctx[rA*3+2]=c02;
    g_ctx[rB*3+0]=c10; g_ctx[rB*3+1]=c11; g_ctx[rB*3+2]=c12;

    if (rA < BB){
        float q[12];
        #pragma unroll
        for (int j=0;j<12;j++) q[j]=sb3[j];
        #pragma unroll
        for (int i=0;i<30;i++){
            float v=b0[i];
            #pragma unroll
            for (int j=0;j<12;j++) q[j]=fmaf(v, sW3[i*15+j], q[j]);
        }
        int b = (int)rA;
        float kl = 0.0f;
        #pragma unroll
        for (int d=0;d<6;d++){
            float qm  = q[d];
            float qlc = clamp6f(q[6+d]);
            float sq  = __expf(qlc);
            float z0  = fmaf(sq, __ldg(eps0 + b*6 + d), qm);
            g_zs[b*6+d] = z0;
            float plc = clamp6f(__ldg(pz0l+d));
            float spz = __expf(plc);
            float dm  = qm - __ldg(pz0m+d);
            kl += (plc - qlc) + (sq*sq + dm*dm)/(2.0f*spz*spz) - 0.5f;
        }
        atomicAdd(&g_acc[1], (double)kl * (1.0/BB));
    }
}

// ---------------- SDE scan: one warp per batch element, 16 warps/block (measured best) ----------------
#define SCAN_WPB 16

__global__ void __launch_bounds__(512,1) k_scan(
    const float* __restrict__ ts,  const float* __restrict__ dW,
    const float* __restrict__ fW1, const float* __restrict__ fb1,
    const float* __restrict__ fW2, const float* __restrict__ fb2,
    const float* __restrict__ hW1, const float* __restrict__ hb1,
    const float* __restrict__ hW2, const float* __restrict__ hb2,
    const float* __restrict__ gW1, const float* __restrict__ gb1,
    const float* __restrict__ gW2, const float* __restrict__ gb2)
{
    __shared__ float s_ts[TT];
    __shared__ float s_hid[SCAN_WPB][264];
    for (int i=threadIdx.x;i<TT;i+=512) s_ts[i]=ts[i];
    __syncthreads();

    int warp = threadIdx.x>>5, lane = threadIdx.x&31;
    int b = blockIdx.x*SCAN_WPB + warp;
    float* H = s_hid[warp];

    float fw[10], hw[7], ga[6], gbv[6], gbi[6];
    float fb=0.f, hb=0.f;
    #pragma unroll
    for (int i=0;i<10;i++) fw[i]=0.f;
    #pragma unroll
    for (int i=0;i<7;i++)  hw[i]=0.f;
    #pragma unroll
    for (int d=0;d<6;d++){ ga[d]=0.f; gbv[d]=0.f; gbi[d]=0.f; }
    if (lane < 30){
        int j = lane;
        fb = fb1[j]; hb = hb1[j];
        #pragma unroll
        for (int i=0;i<10;i++) fw[i]=fW1[i*30+j];
        #pragma unroll
        for (int i=0;i<7;i++)  hw[i]=hW1[i*30+j];
        #pragma unroll
        for (int d=0;d<6;d++){
            ga [d]=gW1[(2*d  )*30+j];
            gbv[d]=gW1[(2*d+1)*30+j];
            gbi[d]=gb1[d*30+j];
        }
    }
    float w2[30]; float b2=0.f; int base=0;
    #pragma unroll
    for (int jj=0;jj<30;jj++) w2[jj]=0.f;
    if (lane < 6){
        base = 0; b2 = fb2[lane];
        #pragma unroll
        for (int jj=0;jj<30;jj++) w2[jj]=fW2[jj*6+lane];
    } else if (lane < 12){
        int oo = lane-6; base = 33; b2 = hb2[oo];
        #pragma unroll
        for (int jj=0;jj<30;jj++) w2[jj]=hW2[jj*6+oo];
    } else if (lane < 18){
        int oo = lane-12; base = 66 + 33*oo; b2 = gb2[oo];
        #pragma unroll
        for (int jj=0;jj<30;jj++) w2[jj]=gW2[oo*30+jj];
    }

    float z[6];
    #pragma unroll
    for (int d=0;d<6;d++) z[d]=g_zs[b*6+d];
    float path = 0.f;

    float c0,c1,c2,dwv;
    {
        const float* cp = g_ctx + ((long)1*BB + b)*3;
        c0=__ldg(cp+0); c1=__ldg(cp+1); c2=__ldg(cp+2);
        dwv = (lane<6)? __ldg(dW + (long)b*6 + lane) : 0.f;
    }

    for (int k=0;k<TT-1;k++){
        float nc0=0.f,nc1=0.f,nc2=0.f,ndw=0.f;
        if (k < TT-2){
            const float* cp = g_ctx + ((long)(k+2)*BB + b)*3;
            nc0=__ldg(cp+0); nc1=__ldg(cp+1); nc2=__ldg(cp+2);
            if (lane<6) ndw = __ldg(dW + ((long)(k+1)*BB + b)*6 + lane);
        }
        float t  = s_ts[k];
        float dt = s_ts[k+1]-t;

        float af = fb;
        af = fmaf(fw[0], t, af);
        #pragma unroll
        for (int d=0;d<6;d++) af = fmaf(fw[1+d], z[d], af);
        af = fmaf(fw[7], c0, af); af = fmaf(fw[8], c1, af); af = fmaf(fw[9], c2, af);
        H[lane] = sp_f(af);

        float ah = hb;
        ah = fmaf(hw[0], t, ah);
        #pragma unroll
        for (int d=0;d<6;d++) ah = fmaf(hw[1+d], z[d], ah);
        H[33+lane] = sp_f(ah);

        #pragma unroll
        for (int d=0;d<6;d++){
            float ag = fmaf(ga[d], t, gbi[d]);
            ag = fmaf(gbv[d], z[d], ag);
            H[66 + 33*d + lane] = sp_f(ag);
        }
        __syncwarp();

        float acc = b2, accB = 0.f;
        #pragma unroll
        for (int jj=0;jj<15;jj++){
            acc  = fmaf(H[base+2*jj  ], w2[2*jj  ], acc );
            accB = fmaf(H[base+2*jj+1], w2[2*jj+1], accB);
        }
        acc += accB;
        __syncwarp();

        float fd = acc;
        float hd = __shfl_sync(0xffffffffu, acc, 6  + lane);
        float gx = __shfl_sync(0xffffffffu, acc, 12 + lane);
        float einv = __expf(-gx);
        float ginv = 1.0f + einv;
        float gg   = __fdividef(1.0f, ginv);
        float u    = (fd - hd) * ginv;
        float us   = (lane < 6) ? u*u : 0.0f;
        us += __shfl_xor_sync(0xffffffffu, us, 1);
        us += __shfl_xor_sync(0xffffffffu, us, 2);
        us += __shfl_xor_sync(0xffffffffu, us, 4);
        path = fmaf(0.5f*dt, us, path);

        float zl = z[0];
        #pragma unroll
        for (int d=1;d<6;d++) if (lane==d) zl=z[d];
        float zn = fmaf(gg, dwv, fmaf(fd, dt, zl));
        if (lane < 6) g_zs[((long)(k+1)*BB + b)*6 + lane] = zn;
        #pragma unroll
        for (int d=0;d<6;d++) z[d] = __shfl_sync(0xffffffffu, zn, d);

        c0=nc0; c1=nc1; c2=nc2; dwv=ndw;
    }
    if (lane == 0) atomicAdd(&g_acc[2], (double)path * (1.0/BB));
}

// ---------------- decoder: 6 -> 30 -> 30 -> 100 + Gaussian loglik, 2 rows/thread ----------------
#define DEC_TPB 256
#define DEC_NT  (NROWS/2)
#define DEC_TSTRIDE 27
#define DEC_TILE (DEC_TPB*DEC_TSTRIDE)
#define DEC_DYN  (2*DEC_TILE*4)

__global__ void __launch_bounds__(DEC_TPB) k_dec(
    const float* __restrict__ xs,
    const float* __restrict__ dW1, const float* __restrict__ db1,
    const float* __restrict__ dW2, const float* __restrict__ db2,
    const float* __restrict__ dW3, const float* __restrict__ db3,
    float* __restrict__ out, int nblocks)
{
    extern __shared__ __align__(16) float dyn[];
    float* tAs = dyn;               // [256][27]
    float* tBs = dyn + DEC_TILE;    // [256][27]
    __shared__ __align__(16) float sW1t[30*8];
    __shared__ __align__(16) float sW2p[30*32];
    __shared__ __align__(16) float sW3t[100*32];
    __shared__ float sb1[30], sb2[30], sb3[100];
    __shared__ float s_red[DEC_TPB/32];

    for (int idx=threadIdx.x; idx<30*8; idx+=DEC_TPB){
        int j=idx>>3, i=idx&7;
        sW1t[idx] = (i<6)? dW1[i*30+j] : 0.0f;
    }
    for (int idx=threadIdx.x; idx<30*32; idx+=DEC_TPB){
        int i=idx>>5, j=idx&31;
        sW2p[idx] = (j<30)? dW2[i*30+j] : 0.0f;
    }
    for (int idx=threadIdx.x; idx<100*32; idx+=DEC_TPB){
        int j=idx>>5, i=idx&31;
        sW3t[idx] = (i<30)? dW3[i*100+j] : 0.0f;
    }
    for (int i=threadIdx.x;i<100; i+=DEC_TPB) sb3[i]=db3[i];
    if (threadIdx.x<30){ sb1[threadIdx.x]=db1[threadIdx.x]; sb2[threadIdx.x]=db2[threadIdx.x]; }
    __syncthreads();

    int t = threadIdx.x;
    long baseA = (long)blockIdx.x*DEC_TPB;
    long baseB = baseA + DEC_NT;
    long rA = baseA + t, rB = baseB + t;

    float zA[6], zB[6];
    {
        const float2* zpA = (const float2*)(g_zs + rA*6);
        const float2* zpB = (const float2*)(g_zs + rB*6);
        #pragma unroll
        for (int q=0;q<3;q++){
            float2 a = __ldg(zpA+q); zA[2*q]=a.x; zA[2*q+1]=a.y;
            float2 bq= __ldg(zpB+q); zB[2*q]=bq.x; zB[2*q+1]=bq.y;
        }
    }

    u64t H2A[15], H2B[15];
    #pragma unroll
    for (int q=0;q<15;q++){ u64t bq = pack2(sb2[2*q], sb2[2*q+1]); H2A[q]=bq; H2B[q]=bq; }
    #pragma unroll 6
    for (int i=0;i<30;i++){
        float4 w0 = ((const float4*)sW1t)[i*2+0];
        float4 w1 = ((const float4*)sW1t)[i*2+1];
        float a = sb1[i], bq = sb1[i];
        a = fmaf(zA[0],w0.x,a); a = fmaf(zA[1],w0.y,a); a = fmaf(zA[2],w0.z,a);
        a = fmaf(zA[3],w0.w,a); a = fmaf(zA[4],w1.x,a); a = fmaf(zA[5],w1.y,a);
        bq= fmaf(zB[0],w0.x,bq); bq= fmaf(zB[1],w0.y,bq); bq= fmaf(zB[2],w0.z,bq);
        bq= fmaf(zB[3],w0.w,bq); bq= fmaf(zB[4],w1.x,bq); bq= fmaf(zB[5],w1.y,bq);
        axpy30x2(H2A, H2B, dup2(sp_f(a)), dup2(sp_f(bq)), sW2p + i*32);
    }
    #pragma unroll
    for (int q=0;q<15;q++){
        float x0,x1,y0,y1;
        unpack2(H2A[q], x0, x1); unpack2(H2B[q], y0, y1);
        H2A[q] = pack2(sp_f(x0), sp_f(x1));
        H2B[q] = pack2(sp_f(y0), sp_f(y1));
    }

    float totA = -50.0f * 0.5f * LOG2PI;
    float totB = -50.0f * 0.5f * LOG2PI;
    for (int ch=0; ch<2; ch++){
        __syncthreads();
        #pragma unroll 5
        for (int k=0;k<25;k++){
            int idx = t + k*DEC_TPB;
            int row = idx/25, col = idx - row*25;
            long gcol = 100 + 25*ch + col;
            tAs[row*DEC_TSTRIDE+col] = __ldg(xs + (baseA+row)*150 + gcol);
            tBs[row*DEC_TSTRIDE+col] = __ldg(xs + (baseB+row)*150 + gcol);
        }
        __syncthreads();
        const float* trA = tAs + t*DEC_TSTRIDE;
        const float* trB = tBs + t*DEC_TSTRIDE;
        for (int jj=0;jj<25;jj++){
            int j = 25*ch + jj;
            float mA,mB,lA,lB;
            dot30x2(H2A, H2B, sW3t + j*32,      sb3[j],    mA, mB);
            dot30x2(H2A, H2B, sW3t + (50+j)*32, sb3[50+j], lA, lB);
            float lcA = clamp6f(lA), lcB = clamp6f(lB);
            float dA = (trA[jj] - mA) * __expf(-lcA);
            float dB = (trB[jj] - mB) * __expf(-lcB);
            totA = fmaf(-0.5f, dA*dA, totA) - lcA;
            totB = fmaf(-0.5f, dB*dB, totB) - lcB;
        }
    }
    float total = totA + totB;

    #pragma unroll
    for (int s=16;s>0;s>>=1) total += __shfl_xor_sync(0xffffffffu, total, s);
    int lane = threadIdx.x&31, warp = threadIdx.x>>5;
    if (lane==0) s_red[warp]=total;
    __syncthreads();
    if (warp==0){
        float v = (lane < DEC_TPB/32) ? s_red[lane] : 0.0f;
        #pragma unroll
        for (int s=4;s>0;s>>=1) v += __shfl_xor_sync(0xffffffffu, v, s);
        if (lane==0){
            atomicAdd(&g_acc[0], (double)v * (1.0/BB));
            __threadfence();
            unsigned d = atomicAdd(&g_done, 1u);
            if (d == (unsigned)(nblocks-1)){
                out[0] = (float)g_acc[0];
                out[1] = (float)(g_acc[1] + g_acc[2]);
                g_acc[0]=0.0; g_acc[1]=0.0; g_acc[2]=0.0;
                g_done = 0u;
            }
        }
    }
}

extern "C" void kernel_launch(void* const* d_in, const int* in_sizes, int n_in,
                              void* d_out, int out_size) {
    const float* xs   = (const float*)d_in[0];
    const float* ts   = (const float*)d_in[1];
    const float* eps0 = (const float*)d_in[2];
    const float* dW   = (const float*)d_in[3];
    const float* eW1  = (const float*)d_in[4];
    const float* eb1  = (const float*)d_in[5];
    const float* eW2  = (const float*)d_in[6];
    const float* eb2  = (const float*)d_in[7];
    const float* eW3  = (const float*)d_in[8];
    const float* eb3  = (const float*)d_in[9];
    const float* dcW1 = (const float*)d_in[10];
    const float* dcb1 = (const float*)d_in[11];
    const float* dcW2 = (const float*)d_in[12];
    const float* dcb2 = (const float*)d_in[13];
    const float* dcW3 = (const float*)d_in[14];
    const float* dcb3 = (const float*)d_in[15];
    const float* fW1  = (const float*)d_in[16];
    const float* fb1  = (const float*)d_in[17];
    const float* fW2  = (const float*)d_in[18];
    const float* fb2  = (const float*)d_in[19];
    const float* hW1  = (const float*)d_in[20];
    const float* hb1  = (const float*)d_in[21];
    const float* hW2  = (const float*)d_in[22];
    const float* hb2  = (const float*)d_in[23];
    const float* gW1  = (const float*)d_in[24];
    const float* gb1  = (const float*)d_in[25];
    const float* gW2  = (const float*)d_in[26];
    const float* gb2  = (const float*)d_in[27];
    const float* pz0m = (const float*)d_in[28];
    const float* pz0l = (const float*)d_in[29];
    float* out = (float*)d_out;

    cudaFuncSetAttribute(k_enc, cudaFuncAttributeMaxDynamicSharedMemorySize, ENC_DYN);
    cudaFuncSetAttribute(k_dec, cudaFuncAttributeMaxDynamicSharedMemorySize, DEC_DYN);

    int dec_blocks = DEC_NT/DEC_TPB;   // 400
    k_enc<<<ENC_NT/ENC_TPB, ENC_TPB, ENC_DYN>>>(xs, eW1,eb1,eW2,eb2,eW3,eb3, eps0, pz0m, pz0l);
    k_scan<<<BB/SCAN_WPB, 512>>>(ts, dW, fW1,fb1,fW2,fb2, hW1,hb1,hW2,hb2, gW1,gb1,gW2,gb2);
    k_dec<<<dec_blocks, DEC_TPB, DEC_DYN>>>(xs, dcW1,dcb1,dcW2,dcb2,dcW3,dcb3, out, dec_blocks);
}

// round 17
// speedup vs baseline: 1.2750x; 1.2750x over previous
#include <cuda_runtime.h>
#include <cuda_bf16.h>

#define TT 100
#define BB 2048
#define NROWS (TT*BB)
#define LOG2PI 1.8378770664093453f

typedef unsigned long long u64t;

// ---------------- packed f32x2 helpers (sm_100+) ----------------
__device__ __forceinline__ u64t pack2(float lo, float hi){
    u64t r; asm("mov.b64 %0, {%1,%2};" : "=l"(r) : "f"(lo), "f"(hi)); return r;
}
__device__ __forceinline__ u64t dup2(float v){ return pack2(v, v); }
__device__ __forceinline__ void unpack2(u64t v, float &lo, float &hi){
    asm("mov.b64 {%0,%1}, %2;" : "=f"(lo), "=f"(hi) : "l"(v));
}
__device__ __forceinline__ void fma2(u64t &d, u64t a, u64t b){
    asm("fma.rn.f32x2 %0, %1, %2, %3;" : "=l"(d) : "l"(a), "l"(b), "l"(d));
}

// ---------------- cp.async helpers ----------------
__device__ __forceinline__ void cp_async8(void* s, const void* g){
    unsigned saddr = (unsigned)__cvta_generic_to_shared(s);
    asm volatile("cp.async.ca.shared.global [%0], [%1], 8;" :: "r"(saddr), "l"(g));
}
#define CP_COMMIT() asm volatile("cp.async.commit_group;" ::: "memory")
#define CP_WAIT0()  asm volatile("cp.async.wait_group 0;" ::: "memory")

// two rows sharing weight loads: acc{0,1}[0..14] += d{0,1} * wrow[0..29]
__device__ __forceinline__ void axpy30x2(u64t* acc0, u64t* acc1, u64t d0, u64t d1,
                                         const float* __restrict__ wrow){
    const ulonglong2* w = (const ulonglong2*)wrow;
    #pragma unroll
    for (int q=0;q<7;q++){
        ulonglong2 ww = w[q];
        fma2(acc0[2*q  ], d0, ww.x); fma2(acc1[2*q  ], d1, ww.x);
        fma2(acc0[2*q+1], d0, ww.y); fma2(acc1[2*q+1], d1, ww.y);
    }
    u64t tail = ((const u64t*)wrow)[14];
    fma2(acc0[14], d0, tail); fma2(acc1[14], d1, tail);
}

// two dot-products (rows A,B) vs one 30-wide weight row; 2 accumulators per row (ILP)
__device__ __forceinline__ void dot30x2(const u64t* hpA, const u64t* hpB,
                                        const float* __restrict__ wrow, float bias,
                                        float &ra, float &rb){
    const ulonglong2* w = (const ulonglong2*)wrow;
    u64t aA0 = pack2(bias, 0.0f), aA1 = pack2(0.0f, 0.0f);
    u64t aB0 = pack2(bias, 0.0f), aB1 = pack2(0.0f, 0.0f);
    #pragma unroll
    for (int q=0;q<7;q++){
        ulonglong2 ww = w[q];
        fma2(aA0, hpA[2*q  ], ww.x); fma2(aB0, hpB[2*q  ], ww.x);
        fma2(aA1, hpA[2*q+1], ww.y); fma2(aB1, hpB[2*q+1], ww.y);
    }
    u64t tail = ((const u64t*)wrow)[14];
    fma2(aA0, hpA[14], tail); fma2(aB0, hpB[14], tail);
    float l0,h0,l1,h1;
    unpack2(aA0,l0,h0); unpack2(aA1,l1,h1); ra = (l0+l1)+(h0+h1);
    unpack2(aB0,l0,h0); unpack2(aB1,l1,h1); rb = (l0+l1)+(h0+h1);
}

// ---------------- scratch ----------------
__device__ float  g_ctx[NROWS*3];
__device__ float  g_zs [NROWS*6];
__device__ double g_acc[3];          // zero at load; finalize block resets after read
__device__ unsigned int g_done;

__device__ __forceinline__ float sp_f(float x){
    float e = __expf(-fabsf(x));
    return fmaxf(x, 0.0f) + __logf(1.0f + e);
}
__device__ __forceinline__ float clamp6f(float x){
    return fminf(fmaxf(x, -6.0f), 6.0f);
}

// ---------------- encoder: 150 -> 30 -> 30 -> {ctx:3, qz0:12}, 2 rows/thread ----------------
// Measured-best (R13): cp.async-staged xs in 5 chunks of 30 floats, packed math,
// 2-row weight sharing.
#define ENC_TPB 128
#define ENC_NT  (NROWS/2)
#define ENC_CH  15                       // float2 per chunk-row
#define ENC_TILE_F2 (ENC_TPB*ENC_CH)     // 1920 float2 per set
#define ENC_DYN (2*ENC_TILE_F2*8)        // 30720 B

__global__ void __launch_bounds__(ENC_TPB) k_enc(
    const float* __restrict__ xs,
    const float* __restrict__ eW1, const float* __restrict__ eb1,
    const float* __restrict__ eW2, const float* __restrict__ eb2,
    const float* __restrict__ eW3, const float* __restrict__ eb3,
    const float* __restrict__ eps0,
    const float* __restrict__ pz0m, const float* __restrict__ pz0l)
{
    extern __shared__ __align__(16) float2 tile[];   // [2][1920]
    float2* tTA = tile;
    float2* tTB = tile + ENC_TILE_F2;
    __shared__ __align__(16) float sW1p[150*32];
    __shared__ __align__(16) float sW2p[30*32];
    __shared__ __align__(16) float sW3c[30*4];
    __shared__ float sW3[450], sb1[30], sb2[30], sb3[15];

    for (int idx=threadIdx.x; idx<150*32; idx+=ENC_TPB){
        int i=idx>>5, j=idx&31;
        sW1p[idx] = (j<30)? eW1[i*30+j] : 0.0f;
    }
    for (int idx=threadIdx.x; idx<30*32; idx+=ENC_TPB){
        int i=idx>>5, j=idx&31;
        sW2p[idx] = (j<30)? eW2[i*30+j] : 0.0f;
    }
    for (int idx=threadIdx.x; idx<30*4; idx+=ENC_TPB){
        int i=idx>>2, c=idx&3;
        sW3c[idx] = (c<3)? eW3[i*15+12+c] : 0.0f;
    }
    for (int i=threadIdx.x;i<450;i+=ENC_TPB) sW3[i]=eW3[i];
    if (threadIdx.x<30){ sb1[threadIdx.x]=eb1[threadIdx.x]; sb2[threadIdx.x]=eb2[threadIdx.x]; }
    if (threadIdx.x<15)  sb3[threadIdx.x]=eb3[threadIdx.x];

    int t = threadIdx.x;
    long baseA = (long)blockIdx.x*ENC_TPB;
    long baseB = baseA + ENC_NT;
    long rA = baseA + t, rB = baseB + t;

    int rowInit = t/15;
    int colInit = t - rowInit*15;

    u64t A0[15], A1[15];
    #pragma unroll
    for (int q=0;q<15;q++){ u64t b = pack2(eb1[2*q], eb1[2*q+1]); A0[q]=b; A1[q]=b; }

    for (int c=0;c<5;c++){
        __syncthreads();
        {
            const float* pA = xs + (baseA + rowInit)*150 + c*30 + colInit*2;
            const float* pB = xs + (baseB + rowInit)*150 + c*30 + colInit*2;
            int col = colInit;
            int sidx = t;
            #pragma unroll
            for (int k=0;k<ENC_CH;k++){
                cp_async8(&tTA[sidx], pA);
                cp_async8(&tTB[sidx], pB);
                sidx += ENC_TPB;
                pA += 1216; pB += 1216;
                col += 8;
                if (col >= 15){ col -= 15; pA += 120; pB += 120; }
            }
        }
        CP_COMMIT(); CP_WAIT0();
        __syncthreads();

        const float2* sA = tTA + t*ENC_CH;
        const float2* sB = tTB + t*ENC_CH;
        #pragma unroll
        for (int q=0;q<ENC_CH;q++){
            float2 vA = sA[q], vB = sB[q];
            int i = c*30 + 2*q;
            axpy30x2(A0, A1, dup2(vA.x), dup2(vB.x), sW1p + (i  )*32);
            axpy30x2(A0, A1, dup2(vA.y), dup2(vB.y), sW1p + (i+1)*32);
        }
    }

    float a0[30], a1[30];
    #pragma unroll
    for (int q=0;q<15;q++){
        unpack2(A0[q], a0[2*q], a0[2*q+1]);
        unpack2(A1[q], a1[2*q], a1[2*q+1]);
    }
    #pragma unroll
    for (int j=0;j<30;j++){ a0[j]=sp_f(a0[j]); a1[j]=sp_f(a1[j]); }

    u64t B0[15], B1[15];
    #pragma unroll
    for (int q=0;q<15;q++){ u64t b = pack2(sb2[2*q], sb2[2*q+1]); B0[q]=b; B1[q]=b; }
    #pragma unroll 6
    for (int i=0;i<30;i++){
        axpy30x2(B0, B1, dup2(a0[i]), dup2(a1[i]), sW2p + i*32);
    }
    float b0[30], b1[30];
    #pragma unroll
    for (int q=0;q<15;q++){
        unpack2(B0[q], b0[2*q], b0[2*q+1]);
        unpack2(B1[q], b1[2*q], b1[2*q+1]);
    }
    #pragma unroll
    for (int j=0;j<30;j++){ b0[j]=sp_f(b0[j]); b1[j]=sp_f(b1[j]); }

    float c00=sb3[12], c01=sb3[13], c02=sb3[14];
    float c10=sb3[12], c11=sb3[13], c12=sb3[14];
    #pragma unroll
    for (int i=0;i<30;i++){
        float4 w = ((const float4*)sW3c)[i];
        c00=fmaf(b0[i],w.x,c00); c01=fmaf(b0[i],w.y,c01); c02=fmaf(b0[i],w.z,c02);
        c10=fmaf(b1[i],w.x,c10); c11=fmaf(b1[i],w.y,c11); c12=fmaf(b1[i],w.z,c12);
    }
    g_ctx[rA*3+0]=c00; g_ctx[rA*3+1]=c01; g_ctx[rA*3+2]=c02;
    g_ctx[rB*3+0]=c10; g_ctx[rB*3+1]=c11; g_ctx[rB*3+2]=c12;

    if (rA < BB){
        float q[12];
        #pragma unroll
        for (int j=0;j<12;j++) q[j]=sb3[j];
        #pragma unroll
        for (int i=0;i<30;i++){
            float v=b0[i];
            #pragma unroll
            for (int j=0;j<12;j++) q[j]=fmaf(v, sW3[i*15+j], q[j]);
        }
        int b = (int)rA;
        float kl = 0.0f;
        #pragma unroll
        for (int d=0;d<6;d++){
            float qm  = q[d];
            float qlc = clamp6f(q[6+d]);
            float sq  = __expf(qlc);
            float z0  = fmaf(sq, __ldg(eps0 + b*6 + d), qm);
            g_zs[b*6+d] = z0;
            float plc = clamp6f(__ldg(pz0l+d));
            float spz = __expf(plc);
            float dm  = qm - __ldg(pz0m+d);
            kl += (plc - qlc) + (sq*sq + dm*dm)/(2.0f*spz*spz) - 0.5f;
        }
        atomicAdd(&g_acc[1], (double)kl * (1.0/BB));
    }
}

// ---------------- SDE scan: one warp per batch element, 16 warps/block (measured best) ----------------
#define SCAN_WPB 16

__global__ void __launch_bounds__(512,1) k_scan(
    const float* __restrict__ ts,  const float* __restrict__ dW,
    const float* __restrict__ fW1, const float* __restrict__ fb1,
    const float* __restrict__ fW2, const float* __restrict__ fb2,
    const float* __restrict__ hW1, const float* __restrict__ hb1,
    const float* __restrict__ hW2, const float* __restrict__ hb2,
    const float* __restrict__ gW1, const float* __restrict__ gb1,
    const float* __restrict__ gW2, const float* __restrict__ gb2)
{
    __shared__ float s_ts[TT];
    __shared__ float s_hid[SCAN_WPB][264];
    for (int i=threadIdx.x;i<TT;i+=512) s_ts[i]=ts[i];
    __syncthreads();

    int warp = threadIdx.x>>5, lane = threadIdx.x&31;
    int b = blockIdx.x*SCAN_WPB + warp;
    float* H = s_hid[warp];

    float fw[10], hw[7], ga[6], gbv[6], gbi[6];
    float fb=0.f, hb=0.f;
    #pragma unroll
    for (int i=0;i<10;i++) fw[i]=0.f;
    #pragma unroll
    for (int i=0;i<7;i++)  hw[i]=0.f;
    #pragma unroll
    for (int d=0;d<6;d++){ ga[d]=0.f; gbv[d]=0.f; gbi[d]=0.f; }
    if (lane < 30){
        int j = lane;
        fb = fb1[j]; hb = hb1[j];
        #pragma unroll
        for (int i=0;i<10;i++) fw[i]=fW1[i*30+j];
        #pragma unroll
        for (int i=0;i<7;i++)  hw[i]=hW1[i*30+j];
        #pragma unroll
        for (int d=0;d<6;d++){
            ga [d]=gW1[(2*d  )*30+j];
            gbv[d]=gW1[(2*d+1)*30+j];
            gbi[d]=gb1[d*30+j];
        }
    }
    float w2[30]; float b2=0.f; int base=0;
    #pragma unroll
    for (int jj=0;jj<30;jj++) w2[jj]=0.f;
    if (lane < 6){
        base = 0; b2 = fb2[lane];
        #pragma unroll
        for (int jj=0;jj<30;jj++) w2[jj]=fW2[jj*6+lane];
    } else if (lane < 12){
        int oo = lane-6; base = 33; b2 = hb2[oo];
        #pragma unroll
        for (int jj=0;jj<30;jj++) w2[jj]=hW2[jj*6+oo];
    } else if (lane < 18){
        int oo = lane-12; base = 66 + 33*oo; b2 = gb2[oo];
        #pragma unroll
        for (int jj=0;jj<30;jj++) w2[jj]=gW2[oo*30+jj];
    }

    float z[6];
    #pragma unroll
    for (int d=0;d<6;d++) z[d]=g_zs[b*6+d];
    float path = 0.f;

    float c0,c1,c2,dwv;
    {
        const float* cp = g_ctx + ((long)1*BB + b)*3;
        c0=__ldg(cp+0); c1=__ldg(cp+1); c2=__ldg(cp+2);
        dwv = (lane<6)? __ldg(dW + (long)b*6 + lane) : 0.f;
    }

    for (int k=0;k<TT-1;k++){
        float nc0=0.f,nc1=0.f,nc2=0.f,ndw=0.f;
        if (k < TT-2){
            const float* cp = g_ctx + ((long)(k+2)*BB + b)*3;
            nc0=__ldg(cp+0); nc1=__ldg(cp+1); nc2=__ldg(cp+2);
            if (lane<6) ndw = __ldg(dW + ((long)(k+1)*BB + b)*6 + lane);
        }
        float t  = s_ts[k];
        float dt = s_ts[k+1]-t;

        float af = fb;
        af = fmaf(fw[0], t, af);
        #pragma unroll
        for (int d=0;d<6;d++) af = fmaf(fw[1+d], z[d], af);
        af = fmaf(fw[7], c0, af); af = fmaf(fw[8], c1, af); af = fmaf(fw[9], c2, af);
        H[lane] = sp_f(af);

        float ah = hb;
        ah = fmaf(hw[0], t, ah);
        #pragma unroll
        for (int d=0;d<6;d++) ah = fmaf(hw[1+d], z[d], ah);
        H[33+lane] = sp_f(ah);

        #pragma unroll
        for (int d=0;d<6;d++){
            float ag = fmaf(ga[d], t, gbi[d]);
            ag = fmaf(gbv[d], z[d], ag);
            H[66 + 33*d + lane] = sp_f(ag);
        }
        __syncwarp();

        float acc = b2, accB = 0.f;
        #pragma unroll
        for (int jj=0;jj<15;jj++){
            acc  = fmaf(H[base+2*jj  ], w2[2*jj  ], acc );
            accB = fmaf(H[base+2*jj+1], w2[2*jj+1], accB);
        }
        acc += accB;
        __syncwarp();

        float fd = acc;
        float hd = __shfl_sync(0xffffffffu, acc, 6  + lane);
        float gx = __shfl_sync(0xffffffffu, acc, 12 + lane);
        float einv = __expf(-gx);
        float ginv = 1.0f + einv;
        float gg   = __fdividef(1.0f, ginv);
        float u    = (fd - hd) * ginv;
        float us   = (lane < 6) ? u*u : 0.0f;
        us += __shfl_xor_sync(0xffffffffu, us, 1);
        us += __shfl_xor_sync(0xffffffffu, us, 2);
        us += __shfl_xor_sync(0xffffffffu, us, 4);
        path = fmaf(0.5f*dt, us, path);

        float zl = z[0];
        #pragma unroll
        for (int d=1;d<6;d++) if (lane==d) zl=z[d];
        float zn = fmaf(gg, dwv, fmaf(fd, dt, zl));
        if (lane < 6) g_zs[((long)(k+1)*BB + b)*6 + lane] = zn;
        #pragma unroll
        for (int d=0;d<6;d++) z[d] = __shfl_sync(0xffffffffu, zn, d);

        c0=nc0; c1=nc1; c2=nc2; dwv=ndw;
    }
    if (lane == 0) atomicAdd(&g_acc[2], (double)path * (1.0/BB));
}

// ---------------- decoder: 6 -> 30 -> 30 -> 100 + Gaussian loglik, 2 rows/thread ----------------
#define DEC_TPB 256
#define DEC_NT  (NROWS/2)
#define DEC_TSTRIDE 27
#define DEC_TILE (DEC_TPB*DEC_TSTRIDE)
#define DEC_DYN  (2*DEC_TILE*4)

__global__ void __launch_bounds__(DEC_TPB) k_dec(
    const float* __restrict__ xs,
    const float* __restrict__ dW1, const float* __restrict__ db1,
    const float* __restrict__ dW2, const float* __restrict__ db2,
    const float* __restrict__ dW3, const float* __restrict__ db3,
    float* __restrict__ out, int nblocks)
{
    extern __shared__ __align__(16) float dyn[];
    float* tAs = dyn;               // [256][27]
    float* tBs = dyn + DEC_TILE;    // [256][27]
    __shared__ __align__(16) float sW1t[30*8];
    __shared__ __align__(16) float sW2p[30*32];
    __shared__ __align__(16) float sW3t[100*32];
    __shared__ float sb1[30], sb2[30], sb3[100];
    __shared__ float s_red[DEC_TPB/32];

    for (int idx=threadIdx.x; idx<30*8; idx+=DEC_TPB){
        int j=idx>>3, i=idx&7;
        sW1t[idx] = (i<6)? dW1[i*30+j] : 0.0f;
    }
    for (int idx=threadIdx.x; idx<30*32; idx+=DEC_TPB){
        int i=idx>>5, j=idx&31;
        sW2p[idx] = (j<30)? dW2[i*30+j] : 0.0f;
    }
    for (int idx=threadIdx.x; idx<100*32; idx+=DEC_TPB){
        int j=idx>>5, i=idx&31;
        sW3t[idx] = (i<30)? dW3[i*100+j] : 0.0f;
    }
    for (int i=threadIdx.x;i<100; i+=DEC_TPB) sb3[i]=db3[i];
    if (threadIdx.x<30){ sb1[threadIdx.x]=db1[threadIdx.x]; sb2[threadIdx.x]=db2[threadIdx.x]; }
    __syncthreads();

    int t = threadIdx.x;
    long baseA = (long)blockIdx.x*DEC_TPB;
    long baseB = baseA + DEC_NT;
    long rA = baseA + t, rB = baseB + t;

    float zA[6], zB[6];
    {
        const float2* zpA = (const float2*)(g_zs + rA*6);
        const float2* zpB = (const float2*)(g_zs + rB*6);
        #pragma unroll
        for (int q=0;q<3;q++){
            float2 a = __ldg(zpA+q); zA[2*q]=a.x; zA[2*q+1]=a.y;
            float2 bq= __ldg(zpB+q); zB[2*q]=bq.x; zB[2*q+1]=bq.y;
        }
    }

    u64t H2A[15], H2B[15];
    #pragma unroll
    for (int q=0;q<15;q++){ u64t bq = pack2(sb2[2*q], sb2[2*q+1]); H2A[q]=bq; H2B[q]=bq; }
    #pragma unroll 6
    for (int i=0;i<30;i++){
        float4 w0 = ((const float4*)sW1t)[i*2+0];
        float4 w1 = ((const float4*)sW1t)[i*2+1];
        float a = sb1[i], bq = sb1[i];
        a = fmaf(zA[0],w0.x,a); a = fmaf(zA[1],w0.y,a); a = fmaf(zA[2],w0.z,a);
        a = fmaf(zA[3],w0.w,a); a = fmaf(zA[4],w1.x,a); a = fmaf(zA[5],w1.y,a);
        bq= fmaf(zB[0],w0.x,bq); bq= fmaf(zB[1],w0.y,bq); bq= fmaf(zB[2],w0.z,bq);
        bq= fmaf(zB[3],w0.w,bq); bq= fmaf(zB[4],w1.x,bq); bq= fmaf(zB[5],w1.y,bq);
        axpy30x2(H2A, H2B, dup2(sp_f(a)), dup2(sp_f(bq)), sW2p + i*32);
    }
    #pragma unroll
    for (int q=0;q<15;q++){
        float x0,x1,y0,y1;
        unpack2(H2A[q], x0, x1); unpack2(H2B[q], y0, y1);
        H2A[q] = pack2(sp_f(x0), sp_f(x1));
        H2B[q] = pack2(sp_f(y0), sp_f(y1));
    }

    float totA = -50.0f * 0.5f * LOG2PI;
    float totB = -50.0f * 0.5f * LOG2PI;
    for (int ch=0; ch<2; ch++){
        __syncthreads();
        #pragma unroll 5
        for (int k=0;k<25;k++){
            int idx = t + k*DEC_TPB;
            int row = idx/25, col = idx - row*25;
            long gcol = 100 + 25*ch + col;
            tAs[row*DEC_TSTRIDE+col] = __ldg(xs + (baseA+row)*150 + gcol);
            tBs[row*DEC_TSTRIDE+col] = __ldg(xs + (baseB+row)*150 + gcol);
        }
        __syncthreads();
        const float* trA = tAs + t*DEC_TSTRIDE;
        const float* trB = tBs + t*DEC_TSTRIDE;
        for (int jj=0;jj<25;jj++){
            int j = 25*ch + jj;
            float mA,mB,lA,lB;
            dot30x2(H2A, H2B, sW3t + j*32,      sb3[j],    mA, mB);
            dot30x2(H2A, H2B, sW3t + (50+j)*32, sb3[50+j], lA, lB);
            float lcA = clamp6f(lA), lcB = clamp6f(lB);
            float dA = (trA[jj] - mA) * __expf(-lcA);
            float dB = (trB[jj] - mB) * __expf(-lcB);
            totA = fmaf(-0.5f, dA*dA, totA) - lcA;
            totB = fmaf(-0.5f, dB*dB, totB) - lcB;
        }
    }
    float total = totA + totB;

    #pragma unroll
    for (int s=16;s>0;s>>=1) total += __shfl_xor_sync(0xffffffffu, total, s);
    int lane = threadIdx.x&31, warp = threadIdx.x>>5;
    if (lane==0) s_red[warp]=total;
    __syncthreads();
    if (warp==0){
        float v = (lane < DEC_TPB/32) ? s_red[lane] : 0.0f;
        #pragma unroll
        for (int s=4;s>0;s>>=1) v += __shfl_xor_sync(0xffffffffu, v, s);
        if (lane==0){
            atomicAdd(&g_acc[0], (double)v * (1.0/BB));
            __threadfence();
            unsigned d = atomicAdd(&g_done, 1u);
            if (d == (unsigned)(nblocks-1)){
                out[0] = (float)g_acc[0];
                out[1] = (float)(g_acc[1] + g_acc[2]);
                g_acc[0]=0.0; g_acc[1]=0.0; g_acc[2]=0.0;
                g_done = 0u;
            }
        }
    }
}

extern "C" void kernel_launch(void* const* d_in, const int* in_sizes, int n_in,
                              void* d_out, int out_size) {
    const float* xs   = (const float*)d_in[0];
    const float* ts   = (const float*)d_in[1];
    const float* eps0 = (const float*)d_in[2];
    const float* dW   = (const float*)d_in[3];
    const float* eW1  = (const float*)d_in[4];
    const float* eb1  = (const float*)d_in[5];
    const float* eW2  = (const float*)d_in[6];
    const float* eb2  = (const float*)d_in[7];
    const float* eW3  = (const float*)d_in[8];
    const float* eb3  = (const float*)d_in[9];
    const float* dcW1 = (const float*)d_in[10];
    const float* dcb1 = (const float*)d_in[11];
    const float* dcW2 = (const float*)d_in[12];
    const float* dcb2 = (const float*)d_in[13];
    const float* dcW3 = (const float*)d_in[14];
    const float* dcb3 = (const float*)d_in[15];
    const float* fW1  = (const float*)d_in[16];
    const float* fb1  = (const float*)d_in[17];
    const float* fW2  = (const float*)d_in[18];
    const float* fb2  = (const float*)d_in[19];
    const float* hW1  = (const float*)d_in[20];
    const float* hb1  = (const float*)d_in[21];
    const float* hW2  = (const float*)d_in[22];
    const float* hb2  = (const float*)d_in[23];
    const float* gW1  = (const float*)d_in[24];
    const float* gb1  = (const float*)d_in[25];
    const float* gW2  = (const float*)d_in[26];
    const float* gb2  = (const float*)d_in[27];
    const float* pz0m = (const float*)d_in[28];
    const float* pz0l = (const float*)d_in[29];
    float* out = (float*)d_out;

    cudaFuncSetAttribute(k_enc, cudaFuncAttributeMaxDynamicSharedMemorySize, ENC_DYN);
    cudaFuncSetAttribute(k_dec, cudaFuncAttributeMaxDynamicSharedMemorySize, DEC_DYN);

    int dec_blocks = DEC_NT/DEC_TPB;   // 400
    k_enc<<<ENC_NT/ENC_TPB, ENC_TPB, ENC_DYN>>>(xs, eW1,eb1,eW2,eb2,eW3,eb3, eps0, pz0m, pz0l);
    k_scan<<<BB/SCAN_WPB, 512>>>(ts, dW, fW1,fb1,fW2,fb2, hW1,hb1,hW2,hb2, gW1,gb1,gW2,gb2);
    k_dec<<<dec_blocks, DEC_TPB, DEC_DYN>>>(xs, dcW1,dcb1,dcW2,dcb2,dcW3,dcb3, out, dec_blocks);
}